// round 15
// baseline (speedup 1.0000x reference)
#include <cuda_runtime.h>
#include <cuda_fp16.h>
#include <stdint.h>

#define G    16
#define NSEQ 4096
#define DD   64
#define CC   128
#define NC   32

// g_Sh holds S^T in fp16 pairs: ST[e][d] = sum_j v[j][e]*k[j][d], exclusive-prefixed by pass2.
__device__ __align__(16) uint32_t g_Sh[2ull * G * NC * DD * DD / 2];
__device__ __align__(16) float g_ksum[2ull * G * NC * DD];

__device__ __forceinline__ uint32_t smem_u32(const void* p) {
    uint32_t a;
    asm("{ .reg .u64 t; cvta.to.shared.u64 t, %1; cvt.u32.u64 %0, t; }" : "=r"(a) : "l"(p));
    return a;
}
#define LDM4(r0, r1, r2, r3, addr) \
    asm volatile("ldmatrix.sync.aligned.m8n8.x4.shared.b16 {%0,%1,%2,%3}, [%4];" \
                 : "=r"(r0), "=r"(r1), "=r"(r2), "=r"(r3) : "r"(addr))
#define LDM4T(r0, r1, r2, r3, addr) \
    asm volatile("ldmatrix.sync.aligned.m8n8.x4.trans.shared.b16 {%0,%1,%2,%3}, [%4];" \
                 : "=r"(r0), "=r"(r1), "=r"(r2), "=r"(r3) : "r"(addr))
__device__ __forceinline__ void mma_f16(float* c, uint32_t a0, uint32_t a1, uint32_t a2, uint32_t a3,
                                        uint32_t b0, uint32_t b1) {
    asm("mma.sync.aligned.m16n8k16.row.col.f32.f16.f16.f32 "
        "{%0,%1,%2,%3},{%4,%5,%6,%7},{%8,%9},{%0,%1,%2,%3};"
        : "+f"(c[0]), "+f"(c[1]), "+f"(c[2]), "+f"(c[3])
        : "r"(a0), "r"(a1), "r"(a2), "r"(a3), "r"(b0), "r"(b1));
}
__device__ __forceinline__ uint32_t packh2(float x, float y) {
    __half2 h = __floats2half2_rn(x, y);
    return *(uint32_t*)&h;
}

// ===========================================================================
// Pass 1 (fp16, 2 chunks/CTA pipelined): ST_m[e][d] = sum_j v[j][e] k_m[j][d].
// Row-major fp16 tiles, pitch 36 words: VH 0, K1H 4608, K2H 9216 -> 13824 w
// ===========================================================================
#define P1_SMEM (13824 * 4)
__global__ __launch_bounds__(256) void pass1_kernel(const float* __restrict__ k1g,
                                                    const float* __restrict__ k2g,
                                                    const float* __restrict__ vg) {
    extern __shared__ uint32_t smw[];
    const int bx = blockIdx.x, g = blockIdx.y;
    const int tid = threadIdx.x, w = tid >> 5, lane = tid & 31;
    const int gq = lane >> 2, tq = lane & 3;
    const int band = (w >> 1) * 16, nh = w & 1;
    const uint32_t sbase = smem_u32(smw);
    const uint32_t lt = ((lane & 7) + ((lane >> 4) & 1) * 8) * 144 + ((lane >> 3) & 1) * 16;
    const uint32_t avh = sbase + lt + (uint32_t)band * 2;

    float4 pv[8], pk1[8];   // chunk-1 prefetch (held across chunk-0 compute)

    #pragma unroll 1
    for (int cc = 0; cc < 2; cc++) {
        const int c = bx * 2 + cc;
        const size_t cbase = ((size_t)g * NSEQ + (size_t)c * CC) * DD;

        if (cc == 0) {
            const float4* srcs[3] = {(const float4*)(vg + cbase), (const float4*)(k1g + cbase),
                                     (const float4*)(k2g + cbase)};
            const int dsts[3] = {0, 4608, 9216};
            #pragma unroll
            for (int t = 0; t < 3; t++) {
                float4 r[8];
                #pragma unroll
                for (int it = 0; it < 8; it++) r[it] = srcs[t][it * 256 + tid];
                #pragma unroll
                for (int it = 0; it < 8; it++) {
                    int wi = (it * 256 + tid) * 2;
                    int off = dsts[t] + (wi >> 5) * 36 + (wi & 31);
                    smw[off]     = packh2(r[it].x, r[it].y);
                    smw[off + 1] = packh2(r[it].z, r[it].w);
                }
            }
        } else {
            // convert prefetched v + k1; load k2 fresh
            #pragma unroll
            for (int it = 0; it < 8; it++) {
                int wi = (it * 256 + tid) * 2;
                int off = (wi >> 5) * 36 + (wi & 31);
                smw[off]            = packh2(pv[it].x, pv[it].y);
                smw[off + 1]        = packh2(pv[it].z, pv[it].w);
                smw[4608 + off]     = packh2(pk1[it].x, pk1[it].y);
                smw[4608 + off + 1] = packh2(pk1[it].z, pk1[it].w);
            }
            {
                const float4* k2p = (const float4*)(k2g + cbase);
                float4 r[8];
                #pragma unroll
                for (int it = 0; it < 8; it++) r[it] = k2p[it * 256 + tid];
                #pragma unroll
                for (int it = 0; it < 8; it++) {
                    int wi = (it * 256 + tid) * 2;
                    int off = 9216 + (wi >> 5) * 36 + (wi & 31);
                    smw[off]     = packh2(r[it].x, r[it].y);
                    smw[off + 1] = packh2(r[it].z, r[it].w);
                }
            }
        }
        __syncthreads();

        if (cc == 0) {   // prefetch chunk 1 (overlaps chunk-0 compute)
            const float4* vp1  = (const float4*)(vg + cbase + (size_t)CC * DD);
            const float4* k1p1 = (const float4*)(k1g + cbase + (size_t)CC * DD);
            #pragma unroll
            for (int it = 0; it < 8; it++) {
                pv[it]  = vp1[it * 256 + tid];
                pk1[it] = k1p1[it * 256 + tid];
            }
        }

        // ksum from staged fp16 k tiles
        if (tid < 128) {
            int m = tid >> 6, d = tid & 63;
            const uint32_t* kb = smw + (m ? 9216 : 4608) + (d >> 1);
            int hi = d & 1;
            float s = 0.f;
            #pragma unroll 16
            for (int j = 0; j < CC; j++) {
                __half2 h = *(const __half2*)&kb[j * 36];
                s += hi ? __high2float(h) : __low2float(h);
            }
            g_ksum[(((size_t)m * G + g) * NC + c) * DD + d] = s;
        }

        #pragma unroll
        for (int m = 0; m < 2; m++) {
            float acc[4][4];
            #pragma unroll
            for (int t = 0; t < 4; t++)
                #pragma unroll
                for (int u = 0; u < 4; u++) acc[t][u] = 0.f;
            const uint32_t bkh = sbase + (m ? 9216u : 4608u) * 4 + lt + (uint32_t)nh * 64;
            #pragma unroll 1
            for (int kk = 0; kk < 8; kk++) {
                uint32_t ah0, ah1, ah2, ah3;
                LDM4T(ah0, ah1, ah2, ah3, avh + kk * 2304);
                #pragma unroll
                for (int p = 0; p < 2; p++) {
                    uint32_t bh0, bh1, bh2, bh3;
                    LDM4T(bh0, bh1, bh2, bh3, bkh + p * 32 + kk * 2304);
                    mma_f16(acc[2 * p],     ah0, ah1, ah2, ah3, bh0, bh2);
                    mma_f16(acc[2 * p + 1], ah0, ah1, ah2, ah3, bh1, bh3);
                }
            }
            uint32_t* Sp = &g_Sh[(((size_t)m * G + g) * NC + c) * 2048];
            #pragma unroll
            for (int t = 0; t < 4; t++) {
                int wcol = nh * 16 + t * 4 + tq;
                int e0 = band + gq;
                Sp[e0 * 32 + wcol]       = packh2(acc[t][0], acc[t][1]);
                Sp[(e0 + 8) * 32 + wcol] = packh2(acc[t][2], acc[t][3]);
            }
        }
        if (cc == 0) __syncthreads();   // chunk-0 smem reads done before overwrite
    }
}

// ===========================================================================
// Pass 2: exclusive prefix over chunks on fp16 storage, f32 running sums.
// ===========================================================================
__global__ __launch_bounds__(128) void pass2_kernel() {
    const int g = blockIdx.x, m = blockIdx.y, h = blockIdx.z, tid = threadIdx.x;
    uint32_t* base = g_Sh + (((size_t)m * G + g) * NC) * 2048 + ((size_t)(h * 128 + tid)) * 2;
    float4 run = make_float4(0.f, 0.f, 0.f, 0.f);
    uint2 buf[8];
    #pragma unroll
    for (int i = 0; i < 8; i++) buf[i] = *(uint2*)(base + (size_t)i * 2048);
    #pragma unroll 8
    for (int c = 0; c < NC; c++) {
        uint2 cur = buf[c & 7];
        if (c + 8 < NC) buf[c & 7] = *(uint2*)(base + (size_t)(c + 8) * 2048);
        uint2 wv;
        wv.x = packh2(run.x, run.y);
        wv.y = packh2(run.z, run.w);
        *(uint2*)(base + (size_t)c * 2048) = wv;
        __half2 a = *(__half2*)&cur.x, b = *(__half2*)&cur.y;
        run.x += __low2float(a); run.y += __high2float(a);
        run.z += __low2float(b); run.w += __high2float(b);
    }
    if (h == 0 && tid < DD) {
        float* kb = &g_ksum[(((size_t)m * G + g) * NC) * DD];
        float fb[8];
        #pragma unroll
        for (int i = 0; i < 8; i++) fb[i] = kb[i * DD + tid];
        float r = 0.f;
        #pragma unroll 8
        for (int c = 0; c < NC; c++) {
            float cu = fb[c & 7];
            if (c + 8 < NC) fb[c & 7] = kb[(c + 8) * DD + tid];
            kb[c * DD + tid] = r;
            r += cu;
        }
    }
}

// ===========================================================================
// Pass 3 (fp16, causal-sparse, deferred v/S staging hidden under stage A).
// ===========================================================================
#define B_KH  34816u
#define B_VH  69632u
#define B_SH  88064u
#define W_KH  8704
#define W_VH  17408
#define W_SH  22016
#define W_QKP 26368
#define W_KP  26496
#define W_DEN 26624
#define W_RED W_KH
#define SMEM3 (26880 * 4)

__global__ __launch_bounds__(512) void pass3_kernel(const float* __restrict__ q1g,
                                                    const float* __restrict__ q2g,
                                                    const float* __restrict__ k1g,
                                                    const float* __restrict__ k2g,
                                                    const float* __restrict__ vg,
                                                    float* __restrict__ outg) {
    extern __shared__ uint32_t smw[];
    const int c = blockIdx.x, g = blockIdx.y, tid = threadIdx.x;
    const int w = tid >> 5, lane = tid & 31;
    const int gq = lane >> 2, tq = lane & 3;
    const int band = (w >> 1) * 16, nh = w & 1;
    const int ilast = band + 15;
    const size_t cbase = ((size_t)g * NSEQ + (size_t)c * CC) * DD;
    float* QKPf = (float*)(smw + W_QKP);
    float* KPf  = (float*)(smw + W_KP);
    float* DENf = (float*)(smw + W_DEN);
    float* REDf = (float*)(smw + W_RED);

    float4 vr[4];
    uint2 s1r[2], s2r[2];

    // ---- stage q/k to smem; v and S only into registers (converted later) ----
    {
        const float4* srcs[4] = {(const float4*)(q1g + cbase), (const float4*)(q2g + cbase),
                                 (const float4*)(k1g + cbase), (const float4*)(k2g + cbase)};
        #pragma unroll
        for (int t = 0; t < 4; t++) {
            float4 r[4];
            #pragma unroll
            for (int it = 0; it < 4; it++) r[it] = srcs[t][it * 512 + tid];
            #pragma unroll
            for (int it = 0; it < 4; it++) {
                int wi = (it * 512 + tid) * 2;
                int off;
                if (t == 0)      off = (wi >> 5) * 68 + (wi & 31);
                else if (t == 1) off = (wi >> 5) * 68 + (wi & 31) + 32;
                else if (t == 2) off = W_KH + (wi >> 5) * 68 + (wi & 31);
                else             off = W_KH + (wi >> 5) * 68 + (wi & 31) + 32;
                smw[off]     = packh2(r[it].x, r[it].y);
                smw[off + 1] = packh2(r[it].z, r[it].w);
            }
        }
        const float4* vp = (const float4*)(vg + cbase);
        #pragma unroll
        for (int it = 0; it < 4; it++) vr[it] = vp[it * 512 + tid];
        const uint2* s1p = (const uint2*)&g_Sh[(((size_t)0 * G + g) * NC + c) * 2048];
        const uint2* s2p = (const uint2*)&g_Sh[(((size_t)1 * G + g) * NC + c) * 2048];
        #pragma unroll
        for (int it = 0; it < 2; it++) { s1r[it] = s1p[it * 512 + tid]; s2r[it] = s2p[it * 512 + tid]; }
        if (tid < DD) {
            KPf[tid]      = g_ksum[(((size_t)0 * G + g) * NC + c) * DD + tid];
            KPf[64 + tid] = g_ksum[(((size_t)1 * G + g) * NC + c) * DD + tid];
        }
    }
    __syncthreads();

    // qkpre from staged fp16 q
    if (tid < CC) {
        float a = 0.f;
        #pragma unroll 8
        for (int wd = 0; wd < 64; wd++) {
            uint32_t qw = smw[tid * 68 + wd];
            __half2 h = *(__half2*)&qw;
            a += __low2float(h) * KPf[2 * wd] + __high2float(h) * KPf[2 * wd + 1];
        }
        QKPf[tid] = a;
    }

    const uint32_t sbase = smem_u32(smw);
    const uint32_t laneoff = ((lane & 7) + ((lane >> 3) & 1) * 8) * 272 + ((lane >> 4) & 1) * 16;
    const uint32_t lt = ((lane & 7) + ((lane >> 4) & 1) * 8) * 144 + ((lane >> 3) & 1) * 16;
    const uint32_t aqh = sbase + band * 272 + laneoff;

    // ---- Stage A: T[band rows][nh col-half], causal-sparse ----
    float accA[8][4];
    #pragma unroll
    for (int t = 0; t < 8; t++)
        #pragma unroll
        for (int u = 0; u < 4; u++) accA[t][u] = 0.f;
    if (nh * 64 <= ilast) {
        const uint32_t bkh = sbase + B_KH + (uint32_t)nh * 17408u + laneoff;
        #pragma unroll 1
        for (int kk = 0; kk < 8; kk++) {
            uint32_t ah0, ah1, ah2, ah3;
            LDM4(ah0, ah1, ah2, ah3, aqh + kk * 32);
            #pragma unroll
            for (int p = 0; p < 4; p++) {
                if (nh * 64 + p * 16 <= ilast) {
                    uint32_t bh0, bh1, bh2, bh3;
                    LDM4(bh0, bh1, bh2, bh3, bkh + p * 4352 + kk * 32);
                    mma_f16(accA[2 * p],     ah0, ah1, ah2, ah3, bh0, bh2);
                    mma_f16(accA[2 * p + 1], ah0, ah1, ah2, ah3, bh1, bh3);
                }
            }
        }
    }

    // ---- epilogue A ----
    const int i0 = band + gq, i1 = i0 + 8;
    uint32_t thA[4][4];
    #pragma unroll
    for (int t = 0; t < 4; t++)
        #pragma unroll
        for (int u = 0; u < 4; u++) thA[t][u] = 0u;
    float rs0 = 0.f, rs1 = 0.f;
    #pragma unroll
    for (int kkt = 0; kkt < 4; kkt++) {
        if (nh * 64 + kkt * 16 <= ilast) {
            int ce = nh * 64 + kkt * 16 + tq * 2, co = ce + 8;
            float e00 = (ce <= i0) ? accA[2 * kkt][0] : 0.f;
            float e01 = (ce + 1 <= i0) ? accA[2 * kkt][1] : 0.f;
            float e10 = (ce <= i1) ? accA[2 * kkt][2] : 0.f;
            float e11 = (ce + 1 <= i1) ? accA[2 * kkt][3] : 0.f;
            float o00 = (co <= i0) ? accA[2 * kkt + 1][0] : 0.f;
            float o01 = (co + 1 <= i0) ? accA[2 * kkt + 1][1] : 0.f;
            float o10 = (co <= i1) ? accA[2 * kkt + 1][2] : 0.f;
            float o11 = (co + 1 <= i1) ? accA[2 * kkt + 1][3] : 0.f;
            rs0 += e00 + e01 + o00 + o01;
            rs1 += e10 + e11 + o10 + o11;
            thA[kkt][0] = packh2(e00, e01);
            thA[kkt][1] = packh2(e10, e11);
            thA[kkt][2] = packh2(o00, o01);
            thA[kkt][3] = packh2(o10, o11);
        }
    }
    rs0 += __shfl_xor_sync(0xFFFFFFFFu, rs0, 1);
    rs0 += __shfl_xor_sync(0xFFFFFFFFu, rs0, 2);
    rs1 += __shfl_xor_sync(0xFFFFFFFFu, rs1, 1);
    rs1 += __shfl_xor_sync(0xFFFFFFFFu, rs1, 2);
    if (tq == 0) {
        DENf[i0 * 2 + nh] = rs0;
        DENf[i1 * 2 + nh] = rs1;
    }

    // ---- deferred conversion: v and S registers -> smem ----
    #pragma unroll
    for (int it = 0; it < 4; it++) {
        int wi = (it * 512 + tid) * 2;
        int off = W_VH + (wi >> 5) * 36 + (wi & 31);
        smw[off]     = packh2(vr[it].x, vr[it].y);
        smw[off + 1] = packh2(vr[it].z, vr[it].w);
    }
    #pragma unroll
    for (int it = 0; it < 2; it++) {
        int wi = (it * 512 + tid) * 2;
        int off = (wi >> 5) * 68 + (wi & 31);
        smw[W_SH + off]      = s1r[it].x;
        smw[W_SH + off + 1]  = s1r[it].y;
        smw[W_SH + off + 32] = s2r[it].x;
        smw[W_SH + off + 33] = s2r[it].y;
    }
    __syncthreads();   // K reads done (RED aliases K); DEN + QKP + VH + SH visible

    // ---- Stage B partials ----
    float accB[8][4];
    #pragma unroll
    for (int t = 0; t < 8; t++)
        #pragma unroll
        for (int u = 0; u < 4; u++) accB[t][u] = 0.f;
    {
        const uint32_t bvh = sbase + B_VH + (uint32_t)nh * 9216u + lt;
        #pragma unroll
        for (int kkt = 0; kkt < 4; kkt++) {
            if (nh * 64 + kkt * 16 <= ilast) {
                #pragma unroll
                for (int p = 0; p < 4; p++) {
                    uint32_t bh0, bh1, bh2, bh3;
                    LDM4T(bh0, bh1, bh2, bh3, bvh + kkt * 2304 + p * 32);
                    mma_f16(accB[2 * p],     thA[kkt][0], thA[kkt][1], thA[kkt][2], thA[kkt][3], bh0, bh2);
                    mma_f16(accB[2 * p + 1], thA[kkt][0], thA[kkt][1], thA[kkt][2], thA[kkt][3], bh1, bh3);
                }
            }
        }
        const uint32_t bsh = sbase + B_SH + laneoff;
        #pragma unroll 1
        for (int kkl = 0; kkl < 4; kkl++) {
            int kk = nh * 4 + kkl;
            uint32_t ah0, ah1, ah2, ah3;
            LDM4(ah0, ah1, ah2, ah3, aqh + kk * 32);
            #pragma unroll
            for (int p = 0; p < 4; p++) {
                uint32_t bh0, bh1, bh2, bh3;
                LDM4(bh0, bh1, bh2, bh3, bsh + p * 4352 + kk * 32);
                mma_f16(accB[2 * p],     ah0, ah1, ah2, ah3, bh0, bh2);
                mma_f16(accB[2 * p + 1], ah0, ah1, ah2, ah3, bh1, bh3);
            }
        }
    }

    // ---- cross-warp reduction + epilogue ----
    if (nh == 1) {
        #pragma unroll
        for (int t = 0; t < 8; t++) {
            int e = t * 8 + tq * 2;
            *(float2*)&REDf[i0 * 64 + e] = make_float2(accB[t][0], accB[t][1]);
            *(float2*)&REDf[i1 * 64 + e] = make_float2(accB[t][2], accB[t][3]);
        }
    }
    __syncthreads();
    if (nh == 0) {
        float dnv0 = 1.0f / (DENf[i0 * 2] + DENf[i0 * 2 + 1] + QKPf[i0] + 1e-10f);
        float dnv1 = 1.0f / (DENf[i1 * 2] + DENf[i1 * 2 + 1] + QKPf[i1] + 1e-10f);
        float* op = outg + cbase;
        #pragma unroll
        for (int t = 0; t < 8; t++) {
            int e = t * 8 + tq * 2;
            float2 p0 = *(const float2*)&REDf[i0 * 64 + e];
            float2 p1 = *(const float2*)&REDf[i1 * 64 + e];
            *(float2*)&op[i0 * DD + e] = make_float2((accB[t][0] + p0.x) * dnv0, (accB[t][1] + p0.y) * dnv0);
            *(float2*)&op[i1 * DD + e] = make_float2((accB[t][2] + p1.x) * dnv1, (accB[t][3] + p1.y) * dnv1);
        }
    }
}

// ---------------------------------------------------------------------------
extern "C" void kernel_launch(void* const* d_in, const int* in_sizes, int n_in,
                              void* d_out, int out_size) {
    const float* q  = (const float*)d_in[0];
    const float* k  = (const float*)d_in[1];
    const float* qr = (const float*)d_in[2];
    const float* kr = (const float*)d_in[3];
    const float* v  = (const float*)d_in[4];
    float* out = (float*)d_out;

    cudaFuncSetAttribute(pass1_kernel, cudaFuncAttributeMaxDynamicSharedMemorySize, P1_SMEM);
    cudaFuncSetAttribute(pass3_kernel, cudaFuncAttributeMaxDynamicSharedMemorySize, SMEM3);

    dim3 g1(NC / 2, G);
    pass1_kernel<<<g1, 256, P1_SMEM>>>(k, kr, v);
    dim3 g2(G, 2, 8);
    pass2_kernel<<<g2, 128>>>();
    dim3 g3(NC, G);
    pass3_kernel<<<g3, 512, SMEM3>>>(q, qr, k, kr, v, out);
}

// round 16
// speedup vs baseline: 1.0504x; 1.0504x over previous
#include <cuda_runtime.h>
#include <cuda_fp16.h>
#include <stdint.h>

#define G    16
#define NSEQ 4096
#define DD   64
#define CC   128
#define NC   32

// g_Sh holds S^T in fp16 pairs: ST[e][d] = sum_j v[j][e]*k[j][d], exclusive-prefixed by pass2.
__device__ __align__(16) uint32_t g_Sh[2ull * G * NC * DD * DD / 2];
__device__ __align__(16) float g_ksum[2ull * G * NC * DD];

__device__ __forceinline__ uint32_t smem_u32(const void* p) {
    uint32_t a;
    asm("{ .reg .u64 t; cvta.to.shared.u64 t, %1; cvt.u32.u64 %0, t; }" : "=r"(a) : "l"(p));
    return a;
}
#define LDM4(r0, r1, r2, r3, addr) \
    asm volatile("ldmatrix.sync.aligned.m8n8.x4.shared.b16 {%0,%1,%2,%3}, [%4];" \
                 : "=r"(r0), "=r"(r1), "=r"(r2), "=r"(r3) : "r"(addr))
#define LDM4T(r0, r1, r2, r3, addr) \
    asm volatile("ldmatrix.sync.aligned.m8n8.x4.trans.shared.b16 {%0,%1,%2,%3}, [%4];" \
                 : "=r"(r0), "=r"(r1), "=r"(r2), "=r"(r3) : "r"(addr))
__device__ __forceinline__ void mma_f16(float* c, uint32_t a0, uint32_t a1, uint32_t a2, uint32_t a3,
                                        uint32_t b0, uint32_t b1) {
    asm("mma.sync.aligned.m16n8k16.row.col.f32.f16.f16.f32 "
        "{%0,%1,%2,%3},{%4,%5,%6,%7},{%8,%9},{%0,%1,%2,%3};"
        : "+f"(c[0]), "+f"(c[1]), "+f"(c[2]), "+f"(c[3])
        : "r"(a0), "r"(a1), "r"(a2), "r"(a3), "r"(b0), "r"(b1));
}
__device__ __forceinline__ uint32_t packh2(float x, float y) {
    __half2 h = __floats2half2_rn(x, y);
    return *(uint32_t*)&h;
}

// ===========================================================================
// Pass 1 (fp16, 2 chunks/CTA pipelined): ST_m[e][d] = sum_j v[j][e] k_m[j][d].
// Row-major fp16 tiles, pitch 36 words: VH 0, K1H 4608, K2H 9216 -> 13824 w
// ===========================================================================
#define P1_SMEM (13824 * 4)
__global__ __launch_bounds__(256) void pass1_kernel(const float* __restrict__ k1g,
                                                    const float* __restrict__ k2g,
                                                    const float* __restrict__ vg) {
    extern __shared__ uint32_t smw[];
    const int bx = blockIdx.x, g = blockIdx.y;
    const int tid = threadIdx.x, w = tid >> 5, lane = tid & 31;
    const int gq = lane >> 2, tq = lane & 3;
    const int band = (w >> 1) * 16, nh = w & 1;
    const uint32_t sbase = smem_u32(smw);
    const uint32_t lt = ((lane & 7) + ((lane >> 4) & 1) * 8) * 144 + ((lane >> 3) & 1) * 16;
    const uint32_t avh = sbase + lt + (uint32_t)band * 2;

    float4 pv[8], pk1[8];   // chunk-1 prefetch (held across chunk-0 compute)

    #pragma unroll 1
    for (int cc = 0; cc < 2; cc++) {
        const int c = bx * 2 + cc;
        const size_t cbase = ((size_t)g * NSEQ + (size_t)c * CC) * DD;

        if (cc == 0) {
            const float4* srcs[3] = {(const float4*)(vg + cbase), (const float4*)(k1g + cbase),
                                     (const float4*)(k2g + cbase)};
            const int dsts[3] = {0, 4608, 9216};
            #pragma unroll
            for (int t = 0; t < 3; t++) {
                float4 r[8];
                #pragma unroll
                for (int it = 0; it < 8; it++) r[it] = srcs[t][it * 256 + tid];
                #pragma unroll
                for (int it = 0; it < 8; it++) {
                    int wi = (it * 256 + tid) * 2;
                    int off = dsts[t] + (wi >> 5) * 36 + (wi & 31);
                    smw[off]     = packh2(r[it].x, r[it].y);
                    smw[off + 1] = packh2(r[it].z, r[it].w);
                }
            }
        } else {
            #pragma unroll
            for (int it = 0; it < 8; it++) {
                int wi = (it * 256 + tid) * 2;
                int off = (wi >> 5) * 36 + (wi & 31);
                smw[off]            = packh2(pv[it].x, pv[it].y);
                smw[off + 1]        = packh2(pv[it].z, pv[it].w);
                smw[4608 + off]     = packh2(pk1[it].x, pk1[it].y);
                smw[4608 + off + 1] = packh2(pk1[it].z, pk1[it].w);
            }
            {
                const float4* k2p = (const float4*)(k2g + cbase);
                float4 r[8];
                #pragma unroll
                for (int it = 0; it < 8; it++) r[it] = k2p[it * 256 + tid];
                #pragma unroll
                for (int it = 0; it < 8; it++) {
                    int wi = (it * 256 + tid) * 2;
                    int off = 9216 + (wi >> 5) * 36 + (wi & 31);
                    smw[off]     = packh2(r[it].x, r[it].y);
                    smw[off + 1] = packh2(r[it].z, r[it].w);
                }
            }
        }
        __syncthreads();

        if (cc == 0) {   // prefetch chunk 1 (overlaps chunk-0 compute)
            const float4* vp1  = (const float4*)(vg + cbase + (size_t)CC * DD);
            const float4* k1p1 = (const float4*)(k1g + cbase + (size_t)CC * DD);
            #pragma unroll
            for (int it = 0; it < 8; it++) {
                pv[it]  = vp1[it * 256 + tid];
                pk1[it] = k1p1[it * 256 + tid];
            }
        }

        // ksum from staged fp16 k tiles
        if (tid < 128) {
            int m = tid >> 6, d = tid & 63;
            const uint32_t* kb = smw + (m ? 9216 : 4608) + (d >> 1);
            int hi = d & 1;
            float s = 0.f;
            #pragma unroll 16
            for (int j = 0; j < CC; j++) {
                __half2 h = *(const __half2*)&kb[j * 36];
                s += hi ? __high2float(h) : __low2float(h);
            }
            g_ksum[(((size_t)m * G + g) * NC + c) * DD + d] = s;
        }

        #pragma unroll
        for (int m = 0; m < 2; m++) {
            float acc[4][4];
            #pragma unroll
            for (int t = 0; t < 4; t++)
                #pragma unroll
                for (int u = 0; u < 4; u++) acc[t][u] = 0.f;
            const uint32_t bkh = sbase + (m ? 9216u : 4608u) * 4 + lt + (uint32_t)nh * 64;
            #pragma unroll 1
            for (int kk = 0; kk < 8; kk++) {
                uint32_t ah0, ah1, ah2, ah3;
                LDM4T(ah0, ah1, ah2, ah3, avh + kk * 2304);
                #pragma unroll
                for (int p = 0; p < 2; p++) {
                    uint32_t bh0, bh1, bh2, bh3;
                    LDM4T(bh0, bh1, bh2, bh3, bkh + p * 32 + kk * 2304);
                    mma_f16(acc[2 * p],     ah0, ah1, ah2, ah3, bh0, bh2);
                    mma_f16(acc[2 * p + 1], ah0, ah1, ah2, ah3, bh1, bh3);
                }
            }
            uint32_t* Sp = &g_Sh[(((size_t)m * G + g) * NC + c) * 2048];
            #pragma unroll
            for (int t = 0; t < 4; t++) {
                int wcol = nh * 16 + t * 4 + tq;
                int e0 = band + gq;
                Sp[e0 * 32 + wcol]       = packh2(acc[t][0], acc[t][1]);
                Sp[(e0 + 8) * 32 + wcol] = packh2(acc[t][2], acc[t][3]);
            }
        }
        if (cc == 0) __syncthreads();   // chunk-0 smem reads done before overwrite
    }
}

// ===========================================================================
// Pass 2: exclusive prefix over chunks on fp16 storage, f32 running sums.
// ===========================================================================
__global__ __launch_bounds__(128) void pass2_kernel() {
    const int g = blockIdx.x, m = blockIdx.y, h = blockIdx.z, tid = threadIdx.x;
    uint32_t* base = g_Sh + (((size_t)m * G + g) * NC) * 2048 + ((size_t)(h * 128 + tid)) * 2;
    float4 run = make_float4(0.f, 0.f, 0.f, 0.f);
    uint2 buf[8];
    #pragma unroll
    for (int i = 0; i < 8; i++) buf[i] = *(uint2*)(base + (size_t)i * 2048);
    #pragma unroll 8
    for (int c = 0; c < NC; c++) {
        uint2 cur = buf[c & 7];
        if (c + 8 < NC) buf[c & 7] = *(uint2*)(base + (size_t)(c + 8) * 2048);
        uint2 wv;
        wv.x = packh2(run.x, run.y);
        wv.y = packh2(run.z, run.w);
        *(uint2*)(base + (size_t)c * 2048) = wv;
        __half2 a = *(__half2*)&cur.x, b = *(__half2*)&cur.y;
        run.x += __low2float(a); run.y += __high2float(a);
        run.z += __low2float(b); run.w += __high2float(b);
    }
    if (h == 0 && tid < DD) {
        float* kb = &g_ksum[(((size_t)m * G + g) * NC) * DD];
        float fb[8];
        #pragma unroll
        for (int i = 0; i < 8; i++) fb[i] = kb[i * DD + tid];
        float r = 0.f;
        #pragma unroll 8
        for (int c = 0; c < NC; c++) {
            float cu = fb[c & 7];
            if (c + 8 < NC) fb[c & 7] = kb[(c + 8) * DD + tid];
            kb[c * DD + tid] = r;
            r += cu;
        }
    }
}

// ===========================================================================
// Pass 3 (fp16, causal-sparse, 512 thr / 16 warps) — R14 version (best known).
// ===========================================================================
#define B_KH  34816u
#define B_VH  69632u
#define B_SH  88064u
#define W_KH  8704
#define W_VH  17408
#define W_SH  22016
#define W_QKP 26368
#define W_KP  26496
#define W_DEN 26624
#define W_RED W_KH
#define SMEM3 (26880 * 4)

__global__ __launch_bounds__(512) void pass3_kernel(const float* __restrict__ q1g,
                                                    const float* __restrict__ q2g,
                                                    const float* __restrict__ k1g,
                                                    const float* __restrict__ k2g,
                                                    const float* __restrict__ vg,
                                                    float* __restrict__ outg) {
    extern __shared__ uint32_t smw[];
    const int c = blockIdx.x, g = blockIdx.y, tid = threadIdx.x;
    const int w = tid >> 5, lane = tid & 31;
    const int gq = lane >> 2, tq = lane & 3;
    const int band = (w >> 1) * 16, nh = w & 1;
    const int ilast = band + 15;
    const size_t cbase = ((size_t)g * NSEQ + (size_t)c * CC) * DD;
    float* QKPf = (float*)(smw + W_QKP);
    float* KPf  = (float*)(smw + W_KP);
    float* DENf = (float*)(smw + W_DEN);
    float* REDf = (float*)(smw + W_RED);

    // ---- register-batched staging (4 LDG.128 in flight per tensor) ----
    {
        const float4* srcs[5] = {(const float4*)(q1g + cbase), (const float4*)(q2g + cbase),
                                 (const float4*)(k1g + cbase), (const float4*)(k2g + cbase),
                                 (const float4*)(vg + cbase)};
        #pragma unroll
        for (int t = 0; t < 5; t++) {
            float4 r[4];
            #pragma unroll
            for (int it = 0; it < 4; it++) r[it] = srcs[t][it * 512 + tid];
            #pragma unroll
            for (int it = 0; it < 4; it++) {
                int wi = (it * 512 + tid) * 2;
                int off;
                if (t == 4)      off = W_VH + (wi >> 5) * 36 + (wi & 31);
                else if (t == 0) off = (wi >> 5) * 68 + (wi & 31);
                else if (t == 1) off = (wi >> 5) * 68 + (wi & 31) + 32;
                else if (t == 2) off = W_KH + (wi >> 5) * 68 + (wi & 31);
                else             off = W_KH + (wi >> 5) * 68 + (wi & 31) + 32;
                smw[off]     = packh2(r[it].x, r[it].y);
                smw[off + 1] = packh2(r[it].z, r[it].w);
            }
        }
        const uint2* s1p = (const uint2*)&g_Sh[(((size_t)0 * G + g) * NC + c) * 2048];
        const uint2* s2p = (const uint2*)&g_Sh[(((size_t)1 * G + g) * NC + c) * 2048];
        uint2 s1r[2], s2r[2];
        #pragma unroll
        for (int it = 0; it < 2; it++) { s1r[it] = s1p[it * 512 + tid]; s2r[it] = s2p[it * 512 + tid]; }
        #pragma unroll
        for (int it = 0; it < 2; it++) {
            int wi = (it * 512 + tid) * 2;
            int off = (wi >> 5) * 68 + (wi & 31);
            smw[W_SH + off]      = s1r[it].x;
            smw[W_SH + off + 1]  = s1r[it].y;
            smw[W_SH + off + 32] = s2r[it].x;
            smw[W_SH + off + 33] = s2r[it].y;
        }
        if (tid < DD) {
            KPf[tid]      = g_ksum[(((size_t)0 * G + g) * NC + c) * DD + tid];
            KPf[64 + tid] = g_ksum[(((size_t)1 * G + g) * NC + c) * DD + tid];
        }
    }
    __syncthreads();

    // qkpre from staged fp16 q
    if (tid < CC) {
        float a = 0.f;
        #pragma unroll 8
        for (int wd = 0; wd < 64; wd++) {
            uint32_t qw = smw[tid * 68 + wd];
            __half2 h = *(__half2*)&qw;
            a += __low2float(h) * KPf[2 * wd] + __high2float(h) * KPf[2 * wd + 1];
        }
        QKPf[tid] = a;
    }

    const uint32_t sbase = smem_u32(smw);
    const uint32_t laneoff = ((lane & 7) + ((lane >> 3) & 1) * 8) * 272 + ((lane >> 4) & 1) * 16;
    const uint32_t lt = ((lane & 7) + ((lane >> 4) & 1) * 8) * 144 + ((lane >> 3) & 1) * 16;
    const uint32_t aqh = sbase + band * 272 + laneoff;

    // ---- Stage A: T[band rows][nh col-half], causal-sparse ----
    float accA[8][4];
    #pragma unroll
    for (int t = 0; t < 8; t++)
        #pragma unroll
        for (int u = 0; u < 4; u++) accA[t][u] = 0.f;
    if (nh * 64 <= ilast) {
        const uint32_t bkh = sbase + B_KH + (uint32_t)nh * 17408u + laneoff;
        #pragma unroll 1
        for (int kk = 0; kk < 8; kk++) {
            uint32_t ah0, ah1, ah2, ah3;
            LDM4(ah0, ah1, ah2, ah3, aqh + kk * 32);
            #pragma unroll
            for (int p = 0; p < 4; p++) {
                if (nh * 64 + p * 16 <= ilast) {
                    uint32_t bh0, bh1, bh2, bh3;
                    LDM4(bh0, bh1, bh2, bh3, bkh + p * 4352 + kk * 32);
                    mma_f16(accA[2 * p],     ah0, ah1, ah2, ah3, bh0, bh2);
                    mma_f16(accA[2 * p + 1], ah0, ah1, ah2, ah3, bh1, bh3);
                }
            }
        }
    }

    // ---- epilogue A ----
    const int i0 = band + gq, i1 = i0 + 8;
    uint32_t thA[4][4];
    #pragma unroll
    for (int t = 0; t < 4; t++)
        #pragma unroll
        for (int u = 0; u < 4; u++) thA[t][u] = 0u;
    float rs0 = 0.f, rs1 = 0.f;
    #pragma unroll
    for (int kkt = 0; kkt < 4; kkt++) {
        if (nh * 64 + kkt * 16 <= ilast) {
            int ce = nh * 64 + kkt * 16 + tq * 2, co = ce + 8;
            float e00 = (ce <= i0) ? accA[2 * kkt][0] : 0.f;
            float e01 = (ce + 1 <= i0) ? accA[2 * kkt][1] : 0.f;
            float e10 = (ce <= i1) ? accA[2 * kkt][2] : 0.f;
            float e11 = (ce + 1 <= i1) ? accA[2 * kkt][3] : 0.f;
            float o00 = (co <= i0) ? accA[2 * kkt + 1][0] : 0.f;
            float o01 = (co + 1 <= i0) ? accA[2 * kkt + 1][1] : 0.f;
            float o10 = (co <= i1) ? accA[2 * kkt + 1][2] : 0.f;
            float o11 = (co + 1 <= i1) ? accA[2 * kkt + 1][3] : 0.f;
            rs0 += e00 + e01 + o00 + o01;
            rs1 += e10 + e11 + o10 + o11;
            thA[kkt][0] = packh2(e00, e01);
            thA[kkt][1] = packh2(e10, e11);
            thA[kkt][2] = packh2(o00, o01);
            thA[kkt][3] = packh2(o10, o11);
        }
    }
    rs0 += __shfl_xor_sync(0xFFFFFFFFu, rs0, 1);
    rs0 += __shfl_xor_sync(0xFFFFFFFFu, rs0, 2);
    rs1 += __shfl_xor_sync(0xFFFFFFFFu, rs1, 1);
    rs1 += __shfl_xor_sync(0xFFFFFFFFu, rs1, 2);
    if (tq == 0) {
        DENf[i0 * 2 + nh] = rs0;
        DENf[i1 * 2 + nh] = rs1;
    }
    __syncthreads();   // K reads done (RED aliases K); DEN + QKP visible

    // ---- Stage B partials ----
    float accB[8][4];
    #pragma unroll
    for (int t = 0; t < 8; t++)
        #pragma unroll
        for (int u = 0; u < 4; u++) accB[t][u] = 0.f;
    {
        const uint32_t bvh = sbase + B_VH + (uint32_t)nh * 9216u + lt;
        #pragma unroll
        for (int kkt = 0; kkt < 4; kkt++) {
            if (nh * 64 + kkt * 16 <= ilast) {
                #pragma unroll
                for (int p = 0; p < 4; p++) {
                    uint32_t bh0, bh1, bh2, bh3;
                    LDM4T(bh0, bh1, bh2, bh3, bvh + kkt * 2304 + p * 32);
                    mma_f16(accB[2 * p],     thA[kkt][0], thA[kkt][1], thA[kkt][2], thA[kkt][3], bh0, bh2);
                    mma_f16(accB[2 * p + 1], thA[kkt][0], thA[kkt][1], thA[kkt][2], thA[kkt][3], bh1, bh3);
                }
            }
        }
        const uint32_t bsh = sbase + B_SH + laneoff;
        #pragma unroll 1
        for (int kkl = 0; kkl < 4; kkl++) {
            int kk = nh * 4 + kkl;
            uint32_t ah0, ah1, ah2, ah3;
            LDM4(ah0, ah1, ah2, ah3, aqh + kk * 32);
            #pragma unroll
            for (int p = 0; p < 4; p++) {
                uint32_t bh0, bh1, bh2, bh3;
                LDM4(bh0, bh1, bh2, bh3, bsh + p * 4352 + kk * 32);
                mma_f16(accB[2 * p],     ah0, ah1, ah2, ah3, bh0, bh2);
                mma_f16(accB[2 * p + 1], ah0, ah1, ah2, ah3, bh1, bh3);
            }
        }
    }

    // ---- cross-warp reduction + epilogue ----
    if (nh == 1) {
        #pragma unroll
        for (int t = 0; t < 8; t++) {
            int e = t * 8 + tq * 2;
            *(float2*)&REDf[i0 * 64 + e] = make_float2(accB[t][0], accB[t][1]);
            *(float2*)&REDf[i1 * 64 + e] = make_float2(accB[t][2], accB[t][3]);
        }
    }
    __syncthreads();
    if (nh == 0) {
        float dnv0 = 1.0f / (DENf[i0 * 2] + DENf[i0 * 2 + 1] + QKPf[i0] + 1e-10f);
        float dnv1 = 1.0f / (DENf[i1 * 2] + DENf[i1 * 2 + 1] + QKPf[i1] + 1e-10f);
        float* op = outg + cbase;
        #pragma unroll
        for (int t = 0; t < 8; t++) {
            int e = t * 8 + tq * 2;
            float2 p0 = *(const float2*)&REDf[i0 * 64 + e];
            float2 p1 = *(const float2*)&REDf[i1 * 64 + e];
            *(float2*)&op[i0 * DD + e] = make_float2((accB[t][0] + p0.x) * dnv0, (accB[t][1] + p0.y) * dnv0);
            *(float2*)&op[i1 * DD + e] = make_float2((accB[t][2] + p1.x) * dnv1, (accB[t][3] + p1.y) * dnv1);
        }
    }
}

// ---------------------------------------------------------------------------
extern "C" void kernel_launch(void* const* d_in, const int* in_sizes, int n_in,
                              void* d_out, int out_size) {
    const float* q  = (const float*)d_in[0];
    const float* k  = (const float*)d_in[1];
    const float* qr = (const float*)d_in[2];
    const float* kr = (const float*)d_in[3];
    const float* v  = (const float*)d_in[4];
    float* out = (float*)d_out;

    cudaFuncSetAttribute(pass1_kernel, cudaFuncAttributeMaxDynamicSharedMemorySize, P1_SMEM);
    cudaFuncSetAttribute(pass3_kernel, cudaFuncAttributeMaxDynamicSharedMemorySize, SMEM3);

    dim3 g1(NC / 2, G);
    pass1_kernel<<<g1, 256, P1_SMEM>>>(k, kr, v);
    dim3 g2(G, 2, 8);
    pass2_kernel<<<g2, 128>>>();
    dim3 g3(NC, G);
    pass3_kernel<<<g3, 512, SMEM3>>>(q, qr, k, kr, v, out);
}

// round 17
// speedup vs baseline: 1.0782x; 1.0265x over previous
#include <cuda_runtime.h>
#include <cuda_fp16.h>
#include <stdint.h>

#define G    16
#define NSEQ 4096
#define DD   64
#define CC   128
#define NC   32

__device__ __align__(16) uint32_t g_Sh[2ull * G * NC * DD * DD / 2];
__device__ __align__(16) float g_ksum[2ull * G * NC * DD];

__device__ __forceinline__ uint32_t smem_u32(const void* p) {
    uint32_t a;
    asm("{ .reg .u64 t; cvta.to.shared.u64 t, %1; cvt.u32.u64 %0, t; }" : "=r"(a) : "l"(p));
    return a;
}
#define LDM4(r0, r1, r2, r3, addr) \
    asm volatile("ldmatrix.sync.aligned.m8n8.x4.shared.b16 {%0,%1,%2,%3}, [%4];" \
                 : "=r"(r0), "=r"(r1), "=r"(r2), "=r"(r3) : "r"(addr))
#define LDM4T(r0, r1, r2, r3, addr) \
    asm volatile("ldmatrix.sync.aligned.m8n8.x4.trans.shared.b16 {%0,%1,%2,%3}, [%4];" \
                 : "=r"(r0), "=r"(r1), "=r"(r2), "=r"(r3) : "r"(addr))
__device__ __forceinline__ void mma_f16(float* c, uint32_t a0, uint32_t a1, uint32_t a2, uint32_t a3,
                                        uint32_t b0, uint32_t b1) {
    asm("mma.sync.aligned.m16n8k16.row.col.f32.f16.f16.f32 "
        "{%0,%1,%2,%3},{%4,%5,%6,%7},{%8,%9},{%0,%1,%2,%3};"
        : "+f"(c[0]), "+f"(c[1]), "+f"(c[2]), "+f"(c[3])
        : "r"(a0), "r"(a1), "r"(a2), "r"(a3), "r"(b0), "r"(b1));
}
__device__ __forceinline__ uint32_t packh2(float x, float y) {
    __half2 h = __floats2half2_rn(x, y);
    return *(uint32_t*)&h;
}

// ===========================================================================
// Pass 1 (unchanged R15/R16): 2 chunks/CTA pipelined.
// ===========================================================================
#define P1_SMEM (13824 * 4)
__global__ __launch_bounds__(256) void pass1_kernel(const float* __restrict__ k1g,
                                                    const float* __restrict__ k2g,
                                                    const float* __restrict__ vg) {
    extern __shared__ uint32_t smw[];
    const int bx = blockIdx.x, g = blockIdx.y;
    const int tid = threadIdx.x, w = tid >> 5, lane = tid & 31;
    const int gq = lane >> 2, tq = lane & 3;
    const int band = (w >> 1) * 16, nh = w & 1;
    const uint32_t sbase = smem_u32(smw);
    const uint32_t lt = ((lane & 7) + ((lane >> 4) & 1) * 8) * 144 + ((lane >> 3) & 1) * 16;
    const uint32_t avh = sbase + lt + (uint32_t)band * 2;

    float4 pv[8], pk1[8];

    #pragma unroll 1
    for (int cc = 0; cc < 2; cc++) {
        const int c = bx * 2 + cc;
        const size_t cbase = ((size_t)g * NSEQ + (size_t)c * CC) * DD;

        if (cc == 0) {
            const float4* srcs[3] = {(const float4*)(vg + cbase), (const float4*)(k1g + cbase),
                                     (const float4*)(k2g + cbase)};
            const int dsts[3] = {0, 4608, 9216};
            #pragma unroll
            for (int t = 0; t < 3; t++) {
                float4 r[8];
                #pragma unroll
                for (int it = 0; it < 8; it++) r[it] = srcs[t][it * 256 + tid];
                #pragma unroll
                for (int it = 0; it < 8; it++) {
                    int wi = (it * 256 + tid) * 2;
                    int off = dsts[t] + (wi >> 5) * 36 + (wi & 31);
                    smw[off]     = packh2(r[it].x, r[it].y);
                    smw[off + 1] = packh2(r[it].z, r[it].w);
                }
            }
        } else {
            #pragma unroll
            for (int it = 0; it < 8; it++) {
                int wi = (it * 256 + tid) * 2;
                int off = (wi >> 5) * 36 + (wi & 31);
                smw[off]            = packh2(pv[it].x, pv[it].y);
                smw[off + 1]        = packh2(pv[it].z, pv[it].w);
                smw[4608 + off]     = packh2(pk1[it].x, pk1[it].y);
                smw[4608 + off + 1] = packh2(pk1[it].z, pk1[it].w);
            }
            {
                const float4* k2p = (const float4*)(k2g + cbase);
                float4 r[8];
                #pragma unroll
                for (int it = 0; it < 8; it++) r[it] = k2p[it * 256 + tid];
                #pragma unroll
                for (int it = 0; it < 8; it++) {
                    int wi = (it * 256 + tid) * 2;
                    int off = 9216 + (wi >> 5) * 36 + (wi & 31);
                    smw[off]     = packh2(r[it].x, r[it].y);
                    smw[off + 1] = packh2(r[it].z, r[it].w);
                }
            }
        }
        __syncthreads();

        if (cc == 0) {
            const float4* vp1  = (const float4*)(vg + cbase + (size_t)CC * DD);
            const float4* k1p1 = (const float4*)(k1g + cbase + (size_t)CC * DD);
            #pragma unroll
            for (int it = 0; it < 8; it++) {
                pv[it]  = vp1[it * 256 + tid];
                pk1[it] = k1p1[it * 256 + tid];
            }
        }

        if (tid < 128) {
            int m = tid >> 6, d = tid & 63;
            const uint32_t* kb = smw + (m ? 9216 : 4608) + (d >> 1);
            int hi = d & 1;
            float s = 0.f;
            #pragma unroll 16
            for (int j = 0; j < CC; j++) {
                __half2 h = *(const __half2*)&kb[j * 36];
                s += hi ? __high2float(h) : __low2float(h);
            }
            g_ksum[(((size_t)m * G + g) * NC + c) * DD + d] = s;
        }

        #pragma unroll
        for (int m = 0; m < 2; m++) {
            float acc[4][4];
            #pragma unroll
            for (int t = 0; t < 4; t++)
                #pragma unroll
                for (int u = 0; u < 4; u++) acc[t][u] = 0.f;
            const uint32_t bkh = sbase + (m ? 9216u : 4608u) * 4 + lt + (uint32_t)nh * 64;
            #pragma unroll 1
            for (int kk = 0; kk < 8; kk++) {
                uint32_t ah0, ah1, ah2, ah3;
                LDM4T(ah0, ah1, ah2, ah3, avh + kk * 2304);
                #pragma unroll
                for (int p = 0; p < 2; p++) {
                    uint32_t bh0, bh1, bh2, bh3;
                    LDM4T(bh0, bh1, bh2, bh3, bkh + p * 32 + kk * 2304);
                    mma_f16(acc[2 * p],     ah0, ah1, ah2, ah3, bh0, bh2);
                    mma_f16(acc[2 * p + 1], ah0, ah1, ah2, ah3, bh1, bh3);
                }
            }
            uint32_t* Sp = &g_Sh[(((size_t)m * G + g) * NC + c) * 2048];
            #pragma unroll
            for (int t = 0; t < 4; t++) {
                int wcol = nh * 16 + t * 4 + tq;
                int e0 = band + gq;
                Sp[e0 * 32 + wcol]       = packh2(acc[t][0], acc[t][1]);
                Sp[(e0 + 8) * 32 + wcol] = packh2(acc[t][2], acc[t][3]);
            }
        }
        if (cc == 0) __syncthreads();
    }
}

// ===========================================================================
// Pass 2 (unchanged).
// ===========================================================================
__global__ __launch_bounds__(128) void pass2_kernel() {
    const int g = blockIdx.x, m = blockIdx.y, h = blockIdx.z, tid = threadIdx.x;
    uint32_t* base = g_Sh + (((size_t)m * G + g) * NC) * 2048 + ((size_t)(h * 128 + tid)) * 2;
    float4 run = make_float4(0.f, 0.f, 0.f, 0.f);
    uint2 buf[8];
    #pragma unroll
    for (int i = 0; i < 8; i++) buf[i] = *(uint2*)(base + (size_t)i * 2048);
    #pragma unroll 8
    for (int c = 0; c < NC; c++) {
        uint2 cur = buf[c & 7];
        if (c + 8 < NC) buf[c & 7] = *(uint2*)(base + (size_t)(c + 8) * 2048);
        uint2 wv;
        wv.x = packh2(run.x, run.y);
        wv.y = packh2(run.z, run.w);
        *(uint2*)(base + (size_t)c * 2048) = wv;
        __half2 a = *(__half2*)&cur.x, b = *(__half2*)&cur.y;
        run.x += __low2float(a); run.y += __high2float(a);
        run.z += __low2float(b); run.w += __high2float(b);
    }
    if (h == 0 && tid < DD) {
        float* kb = &g_ksum[(((size_t)m * G + g) * NC) * DD];
        float fb[8];
        #pragma unroll
        for (int i = 0; i < 8; i++) fb[i] = kb[i * DD + tid];
        float r = 0.f;
        #pragma unroll 8
        for (int c = 0; c < NC; c++) {
            float cu = fb[c & 7];
            if (c + 8 < NC) fb[c & 7] = kb[(c + 8) * DD + tid];
            kb[c * DD + tid] = r;
            r += cu;
        }
    }
}

// ===========================================================================
// Pass 3 v2: 256 thr / 8 warps, 2 CTAs/SM. Warp owns 16 rows x full 128 cols,
// processing the two column halves sequentially (accA reused). No cross-warp
// reduction. smem: QH 0  KH 8704  VH 17408  SH 22016  QKP 26368  KP 26496
// ===========================================================================
#define B_KH  34816u
#define B_VH  69632u
#define B_SH  88064u
#define W_KH  8704
#define W_VH  17408
#define W_SH  22016
#define W_QKP 26368
#define W_KP  26496
#define SMEM3 (26624 * 4)

__global__ void __launch_bounds__(256, 2) pass3_kernel(const float* __restrict__ q1g,
                                                       const float* __restrict__ q2g,
                                                       const float* __restrict__ k1g,
                                                       const float* __restrict__ k2g,
                                                       const float* __restrict__ vg,
                                                       float* __restrict__ outg) {
    extern __shared__ uint32_t smw[];
    const int c = blockIdx.x, g = blockIdx.y, tid = threadIdx.x;
    const int w = tid >> 5, lane = tid & 31;
    const int gq = lane >> 2, tq = lane & 3;
    const int band = w * 16;
    const int ilast = band + 15;
    const size_t cbase = ((size_t)g * NSEQ + (size_t)c * CC) * DD;
    float* QKPf = (float*)(smw + W_QKP);
    float* KPf  = (float*)(smw + W_KP);

    // ---- staging (256 thr, register-batched) ----
    {
        const float4* srcs[5] = {(const float4*)(q1g + cbase), (const float4*)(q2g + cbase),
                                 (const float4*)(k1g + cbase), (const float4*)(k2g + cbase),
                                 (const float4*)(vg + cbase)};
        #pragma unroll
        for (int t = 0; t < 5; t++) {
            float4 r[8];
            #pragma unroll
            for (int it = 0; it < 8; it++) r[it] = srcs[t][it * 256 + tid];
            #pragma unroll
            for (int it = 0; it < 8; it++) {
                int wi = (it * 256 + tid) * 2;
                int off;
                if (t == 4)      off = W_VH + (wi >> 5) * 36 + (wi & 31);
                else if (t == 0) off = (wi >> 5) * 68 + (wi & 31);
                else if (t == 1) off = (wi >> 5) * 68 + (wi & 31) + 32;
                else if (t == 2) off = W_KH + (wi >> 5) * 68 + (wi & 31);
                else             off = W_KH + (wi >> 5) * 68 + (wi & 31) + 32;
                smw[off]     = packh2(r[it].x, r[it].y);
                smw[off + 1] = packh2(r[it].z, r[it].w);
            }
        }
        const uint2* s1p = (const uint2*)&g_Sh[(((size_t)0 * G + g) * NC + c) * 2048];
        const uint2* s2p = (const uint2*)&g_Sh[(((size_t)1 * G + g) * NC + c) * 2048];
        uint2 s1r[4], s2r[4];
        #pragma unroll
        for (int it = 0; it < 4; it++) { s1r[it] = s1p[it * 256 + tid]; s2r[it] = s2p[it * 256 + tid]; }
        #pragma unroll
        for (int it = 0; it < 4; it++) {
            int wi = (it * 256 + tid) * 2;
            int off = (wi >> 5) * 68 + (wi & 31);
            smw[W_SH + off]      = s1r[it].x;
            smw[W_SH + off + 1]  = s1r[it].y;
            smw[W_SH + off + 32] = s2r[it].x;
            smw[W_SH + off + 33] = s2r[it].y;
        }
        if (tid < DD) {
            KPf[tid]      = g_ksum[(((size_t)0 * G + g) * NC + c) * DD + tid];
            KPf[64 + tid] = g_ksum[(((size_t)1 * G + g) * NC + c) * DD + tid];
        }
    }
    __syncthreads();

    // qkpre
    if (tid < CC) {
        float a = 0.f;
        #pragma unroll 8
        for (int wd = 0; wd < 64; wd++) {
            uint32_t qw = smw[tid * 68 + wd];
            __half2 h = *(__half2*)&qw;
            a += __low2float(h) * KPf[2 * wd] + __high2float(h) * KPf[2 * wd + 1];
        }
        QKPf[tid] = a;
    }
    __syncthreads();

    const uint32_t sbase = smem_u32(smw);
    const uint32_t laneoff = ((lane & 7) + ((lane >> 3) & 1) * 8) * 272 + ((lane >> 4) & 1) * 16;
    const uint32_t lt = ((lane & 7) + ((lane >> 4) & 1) * 8) * 144 + ((lane >> 3) & 1) * 16;
    const uint32_t aqh = sbase + band * 272 + laneoff;
    const int i0 = band + gq, i1 = i0 + 8;

    float accB[8][4];
    #pragma unroll
    for (int t = 0; t < 8; t++)
        #pragma unroll
        for (int u = 0; u < 4; u++) accB[t][u] = 0.f;
    float rs0 = 0.f, rs1 = 0.f;

    #pragma unroll 1
    for (int nh = 0; nh < 2; nh++) {
        if (nh * 64 > ilast) break;   // fully above diagonal
        // ---- stage A for this column half ----
        float accA[8][4];
        #pragma unroll
        for (int t = 0; t < 8; t++)
            #pragma unroll
            for (int u = 0; u < 4; u++) accA[t][u] = 0.f;
        {
            const uint32_t bkh = sbase + B_KH + (uint32_t)nh * 17408u + laneoff;
            #pragma unroll 1
            for (int kk = 0; kk < 8; kk++) {
                uint32_t ah0, ah1, ah2, ah3;
                LDM4(ah0, ah1, ah2, ah3, aqh + kk * 32);
                #pragma unroll
                for (int p = 0; p < 4; p++) {
                    if (nh * 64 + p * 16 <= ilast) {
                        uint32_t bh0, bh1, bh2, bh3;
                        LDM4(bh0, bh1, bh2, bh3, bkh + p * 4352 + kk * 32);
                        mma_f16(accA[2 * p],     ah0, ah1, ah2, ah3, bh0, bh2);
                        mma_f16(accA[2 * p + 1], ah0, ah1, ah2, ah3, bh1, bh3);
                    }
                }
            }
        }
        // ---- epilogue: mask, row sums, pack ----
        uint32_t thA[4][4];
        #pragma unroll
        for (int t = 0; t < 4; t++)
            #pragma unroll
            for (int u = 0; u < 4; u++) thA[t][u] = 0u;
        #pragma unroll
        for (int kkt = 0; kkt < 4; kkt++) {
            if (nh * 64 + kkt * 16 <= ilast) {
                int ce = nh * 64 + kkt * 16 + tq * 2, co = ce + 8;
                float e00 = (ce <= i0) ? accA[2 * kkt][0] : 0.f;
                float e01 = (ce + 1 <= i0) ? accA[2 * kkt][1] : 0.f;
                float e10 = (ce <= i1) ? accA[2 * kkt][2] : 0.f;
                float e11 = (ce + 1 <= i1) ? accA[2 * kkt][3] : 0.f;
                float o00 = (co <= i0) ? accA[2 * kkt + 1][0] : 0.f;
                float o01 = (co + 1 <= i0) ? accA[2 * kkt + 1][1] : 0.f;
                float o10 = (co <= i1) ? accA[2 * kkt + 1][2] : 0.f;
                float o11 = (co + 1 <= i1) ? accA[2 * kkt + 1][3] : 0.f;
                rs0 += e00 + e01 + o00 + o01;
                rs1 += e10 + e11 + o10 + o11;
                thA[kkt][0] = packh2(e00, e01);
                thA[kkt][1] = packh2(e10, e11);
                thA[kkt][2] = packh2(o00, o01);
                thA[kkt][3] = packh2(o10, o11);
            }
        }
        // ---- T v for this j-half ----
        {
            const uint32_t bvh = sbase + B_VH + (uint32_t)nh * 9216u + lt;
            #pragma unroll
            for (int kkt = 0; kkt < 4; kkt++) {
                if (nh * 64 + kkt * 16 <= ilast) {
                    #pragma unroll
                    for (int p = 0; p < 4; p++) {
                        uint32_t bh0, bh1, bh2, bh3;
                        LDM4T(bh0, bh1, bh2, bh3, bvh + kkt * 2304 + p * 32);
                        mma_f16(accB[2 * p],     thA[kkt][0], thA[kkt][1], thA[kkt][2], thA[kkt][3], bh0, bh2);
                        mma_f16(accB[2 * p + 1], thA[kkt][0], thA[kkt][1], thA[kkt][2], thA[kkt][3], bh1, bh3);
                    }
                }
            }
        }
    }

    // ---- q Scat (full K) ----
    {
        const uint32_t bsh = sbase + B_SH + laneoff;
        #pragma unroll 1
        for (int kk = 0; kk < 8; kk++) {
            uint32_t ah0, ah1, ah2, ah3;
            LDM4(ah0, ah1, ah2, ah3, aqh + kk * 32);
            #pragma unroll
            for (int p = 0; p < 4; p++) {
                uint32_t bh0, bh1, bh2, bh3;
                LDM4(bh0, bh1, bh2, bh3, bsh + p * 4352 + kk * 32);
                mma_f16(accB[2 * p],     ah0, ah1, ah2, ah3, bh0, bh2);
                mma_f16(accB[2 * p + 1], ah0, ah1, ah2, ah3, bh1, bh3);
            }
        }
    }

    // ---- epilogue B: in-warp row sums, divide, store ----
    rs0 += __shfl_xor_sync(0xFFFFFFFFu, rs0, 1);
    rs0 += __shfl_xor_sync(0xFFFFFFFFu, rs0, 2);
    rs1 += __shfl_xor_sync(0xFFFFFFFFu, rs1, 1);
    rs1 += __shfl_xor_sync(0xFFFFFFFFu, rs1, 2);
    float dnv0 = 1.0f / (rs0 + QKPf[i0] + 1e-10f);
    float dnv1 = 1.0f / (rs1 + QKPf[i1] + 1e-10f);
    float* op = outg + cbase;
    #pragma unroll
    for (int t = 0; t < 8; t++) {
        int e = t * 8 + tq * 2;
        *(float2*)&op[i0 * DD + e] = make_float2(accB[t][0] * dnv0, accB[t][1] * dnv0);
        *(float2*)&op[i1 * DD + e] = make_float2(accB[t][2] * dnv1, accB[t][3] * dnv1);
    }
}

// ---------------------------------------------------------------------------
extern "C" void kernel_launch(void* const* d_in, const int* in_sizes, int n_in,
                              void* d_out, int out_size) {
    const float* q  = (const float*)d_in[0];
    const float* k  = (const float*)d_in[1];
    const float* qr = (const float*)d_in[2];
    const float* kr = (const float*)d_in[3];
    const float* v  = (const float*)d_in[4];
    float* out = (float*)d_out;

    cudaFuncSetAttribute(pass1_kernel, cudaFuncAttributeMaxDynamicSharedMemorySize, P1_SMEM);
    cudaFuncSetAttribute(pass3_kernel, cudaFuncAttributeMaxDynamicSharedMemorySize, SMEM3);

    dim3 g1(NC / 2, G);
    pass1_kernel<<<g1, 256, P1_SMEM>>>(k, kr, v);
    dim3 g2(G, 2, 8);
    pass2_kernel<<<g2, 128>>>();
    dim3 g3(NC, G);
    pass3_kernel<<<g3, 256, SMEM3>>>(q, qr, k, kr, v, out);
}